// round 13
// baseline (speedup 1.0000x reference)
#include <cuda_runtime.h>
#include <math.h>

#define NSAMP 8192
#define SEQ   (NSAMP*3)      /* 24576 sequential LSTM steps */
#define E     1024
#define HH    1024
#define G4    4096
#define RULED 32
#define OUTD  2
#define NCTA  128
#define POISON 0xFFFFFFFFu   /* NaN bit pattern; h in (-1,1), canary=0, never match */

/* Static device scratch — 256B-aligned so vector (128-bit) accesses are legal */
__device__ __align__(256) float g_X [(size_t)SEQ * E];          /* ~100 MB */
__device__ __align__(256) float g_Gx[(size_t)SEQ * G4];         /* ~403 MB */
__device__ __align__(256) float g_h [(size_t)(SEQ + 1) * HH];   /* ~100 MB */
__device__ __align__(256) float g_cn[(size_t)(SEQ + 1) * NCTA]; /* ~12.6 MB canaries */

/* ------------------------------------------------------------------ */
/* Init: h row 0 = 0, canary row 0 = 0 (valid); everything else NaN.  */
__global__ __launch_bounds__(256) void poison_k()
{
    const size_t th = (size_t)(SEQ + 1) * HH;
    unsigned* p = (unsigned*)g_h;
    for (size_t i = (size_t)blockIdx.x * 256 + threadIdx.x; i < th;
         i += (size_t)gridDim.x * 256)
        p[i] = (i < HH) ? 0u : POISON;
    const size_t tc = (size_t)(SEQ + 1) * NCTA;
    unsigned* q = (unsigned*)g_cn;
    for (size_t i = (size_t)blockIdx.x * 256 + threadIdx.x; i < tc;
         i += (size_t)gridDim.x * 256)
        q[i] = (i < NCTA) ? 0u : POISON;
}

/* ------------------------------------------------------------------ */
/* Build X: row 3n = rules@W_rule + b_rule, rows 3n+1/2 = face gather */
__global__ __launch_bounds__(256) void build_x_k(
    const float* __restrict__ rules, const int* __restrict__ id1,
    const int* __restrict__ id2, const float* __restrict__ W_rule,
    const float* __restrict__ b_rule, const float* __restrict__ face)
{
    int s = blockIdx.x;
    int n = s / 3, t = s - n * 3;
    float* dst = g_X + (size_t)s * E;
    if (t == 0) {
        __shared__ float r[RULED];
        if (threadIdx.x < RULED) r[threadIdx.x] = rules[n * RULED + threadIdx.x];
        __syncthreads();
        for (int e = threadIdx.x; e < E; e += 256) {
            float acc = b_rule[e];
            #pragma unroll
            for (int k = 0; k < RULED; ++k) acc += r[k] * W_rule[k * E + e];
            dst[e] = acc;
        }
    } else {
        int id = (t == 1 ? id1 : id2)[n];
        const float4* src = (const float4*)(face + (size_t)id * E);
        float4* d4 = (float4*)dst;
        for (int i = threadIdx.x; i < E / 4; i += 256) d4[i] = src[i];
    }
}

/* ------------------------------------------------------------------ */
/* Gx[s][r] = dot(X[s,:], W_ih[r,:]) + b_ih[r] + b_hh[r]  (C = A B^T) */
#define BM 128
#define BN 128
#define BK 16
__global__ __launch_bounds__(256) void gemm_gx_k(
    const float* __restrict__ B,          /* W_ih [4096][1024] */
    const float* __restrict__ bih, const float* __restrict__ bhh)
{
    __shared__ float As[BK][BM + 4];
    __shared__ float Bs[BK][BN + 4];
    const int bm = blockIdx.y * BM;
    const int bn = blockIdx.x * BN;
    const int tid = threadIdx.x;
    const int ty = tid >> 4, tx = tid & 15;
    float acc[8][8] = {};
    const float* A = g_X;

    for (int k0 = 0; k0 < E; k0 += BK) {
        #pragma unroll
        for (int v = 0; v < 2; ++v) {
            int f4  = tid * 2 + v;
            int row = f4 >> 2;
            int kq  = f4 & 3;
            float4 a = *(const float4*)(A + (size_t)(bm + row) * E + k0 + kq * 4);
            As[kq*4+0][row] = a.x; As[kq*4+1][row] = a.y;
            As[kq*4+2][row] = a.z; As[kq*4+3][row] = a.w;
            float4 b = *(const float4*)(B + (size_t)(bn + row) * E + k0 + kq * 4);
            Bs[kq*4+0][row] = b.x; Bs[kq*4+1][row] = b.y;
            Bs[kq*4+2][row] = b.z; Bs[kq*4+3][row] = b.w;
        }
        __syncthreads();
        #pragma unroll
        for (int k = 0; k < BK; ++k) {
            float ar[8], br[8];
            #pragma unroll
            for (int i = 0; i < 8; ++i) ar[i] = As[k][ty*8 + i];
            #pragma unroll
            for (int i = 0; i < 8; ++i) br[i] = Bs[k][tx*8 + i];
            #pragma unroll
            for (int i = 0; i < 8; ++i)
                #pragma unroll
                for (int j = 0; j < 8; ++j) acc[i][j] += ar[i] * br[j];
        }
        __syncthreads();
    }
    #pragma unroll
    for (int i = 0; i < 8; ++i) {
        size_t row = (size_t)(bm + ty*8 + i);
        #pragma unroll
        for (int j = 0; j < 8; ++j) {
            int col = bn + tx*8 + j;
            g_Gx[row * G4 + col] = acc[i][j] + bih[col] + bhh[col];
        }
    }
}

/* ------------------------------------------------------------------ */
/* Persistent sequential LSTM. 128 CTAs x 256 threads, 1 CTA/SM.      */
/* Compute core is byte-for-byte R5 (the fastest measured body).      */
/* Sync: canary gate — warp 0 polls 512B of per-CTA canaries (hot L2  */
/* lines) instead of 32K threads polling 4KB of h. h fetched once     */
/* post-gate with a poison RE-CHECK loop, so correctness never relies */
/* on store ordering (no fence on the critical path).                 */
__global__ __launch_bounds__(256, 1) void lstm_seq_k(const float* __restrict__ Whh)
{
    const int b    = blockIdx.x;
    const int tid  = threadIdx.x;
    const int warp = tid >> 5;
    const int lane = tid & 31;
    const int j    = b * 8 + warp;

    /* Weight registers: w[q][i] = W_hh[q*1024 + j][lane + 32*i]  (R5) */
    float w[4][32];
    #pragma unroll
    for (int q = 0; q < 4; ++q) {
        const float* wr = Whh + (size_t)(q * HH + j) * HH;
        #pragma unroll
        for (int i = 0; i < 32; ++i) w[q][i] = wr[lane + 32 * i];
    }

    __shared__ __align__(16) float hs[2][HH];   /* double buffer */
    float c = 0.0f;

    for (int t = 0; t < SEQ; ++t) {
        /* gate-bias prefetch (independent of h; overlaps the gate)    */
        float gq = 0.0f;
        if (lane < 4) gq = __ldg(&g_Gx[(size_t)t * G4 + lane * HH + j]);

        /* GATE: warp 0 polls the 128 canaries of step t (512B total,
           R5's proven volatile poll shape on 4 hot cache lines).      */
        if (warp == 0) {
            volatile const unsigned* cp =
                (const unsigned*)g_cn + (size_t)t * NCTA + 4 * lane;
            unsigned c0 = cp[0], c1 = cp[1], c2 = cp[2], c3 = cp[3];
            while (c0 == POISON || c1 == POISON || c2 == POISON || c3 == POISON) {
                c0 = cp[0]; c1 = cp[1]; c2 = cp[2]; c3 = cp[3];
            }
        }
        __syncthreads();                          /* B-gate */

        /* h fetch: one 16B load per thread; poison re-check loop
           protects against canary/h store reordering (rare path).    */
        const uint4* hp = (const uint4*)(g_h + (size_t)t * HH) + tid;
        uint4 hv = __ldcg(hp);
        while (hv.x == POISON || hv.y == POISON ||
               hv.z == POISON || hv.w == POISON) {
            volatile const unsigned* s =
                (const unsigned*)g_h + (size_t)t * HH + 4 * tid;
            hv.x = s[0]; hv.y = s[1]; hv.z = s[2]; hv.w = s[3];
        }

        const int p = t & 1;
        *(float4*)&hs[p][4 * tid] =
            make_float4(__uint_as_float(hv.x), __uint_as_float(hv.y),
                        __uint_as_float(hv.z), __uint_as_float(hv.w));
        __syncthreads();                          /* B-stage */

        /* R5 dot: 4 gate rows, k strided by lane (bank-conflict free) */
        float a0 = 0.f, a1 = 0.f, a2 = 0.f, a3 = 0.f;
        #pragma unroll
        for (int i = 0; i < 32; ++i) {
            float hvv = hs[p][lane + 32 * i];
            a0 += w[0][i] * hvv; a1 += w[1][i] * hvv;
            a2 += w[2][i] * hvv; a3 += w[3][i] * hvv;
        }
        #pragma unroll
        for (int off = 16; off; off >>= 1) {
            a0 += __shfl_xor_sync(0xffffffffu, a0, off);
            a1 += __shfl_xor_sync(0xffffffffu, a1, off);
            a2 += __shfl_xor_sync(0xffffffffu, a2, off);
            a3 += __shfl_xor_sync(0xffffffffu, a3, off);
        }

        /* R5 activations: lanes 0..3 compute i,f,g,o in parallel      */
        float pre = ((lane == 0) ? a0 : (lane == 1) ? a1 :
                     (lane == 2) ? a2 : a3) + gq;
        float act = (lane == 2) ? __tanhf(pre)
                                : __fdividef(1.0f, 1.0f + __expf(-pre));
        float iact = __shfl_sync(0xffffffffu, act, 0);
        float fact = __shfl_sync(0xffffffffu, act, 1);
        float gact = __shfl_sync(0xffffffffu, act, 2);
        float oact = __shfl_sync(0xffffffffu, act, 3);

        c = fact * c + iact * gact;
        float hn = oact * __tanhf(c);

        /* publish h(t+1) (R5 style), then barrier, then canary store.
           Plain store — no atomics, no serialization.                 */
        if (lane == 0)
            __stcg(g_h + (size_t)(t + 1) * HH + j, hn);
        __syncthreads();                          /* B-pub */
        if (tid == 32)
            __stcg(g_cn + (size_t)(t + 1) * NCTA + b, 0.0f);
    }
}

/* ------------------------------------------------------------------ */
/* out[n] = h(after sample n) @ W_out + b_out                          */
__global__ __launch_bounds__(256) void out_k(
    const float* __restrict__ Wout, const float* __restrict__ bout,
    float* __restrict__ out)
{
    int n = blockIdx.x;
    const float* h = g_h + (size_t)(3 * n + 3) * HH;
    float p0 = 0.f, p1 = 0.f;
    for (int jj = threadIdx.x; jj < HH; jj += 256) {
        float hv = h[jj];
        p0 += hv * Wout[jj * 2 + 0];
        p1 += hv * Wout[jj * 2 + 1];
    }
    __shared__ float s0[256], s1[256];
    s0[threadIdx.x] = p0; s1[threadIdx.x] = p1;
    __syncthreads();
    for (int st = 128; st; st >>= 1) {
        if (threadIdx.x < st) {
            s0[threadIdx.x] += s0[threadIdx.x + st];
            s1[threadIdx.x] += s1[threadIdx.x + st];
        }
        __syncthreads();
    }
    if (threadIdx.x == 0) {
        out[n * 2 + 0] = s0[0] + bout[0];
        out[n * 2 + 1] = s1[0] + bout[1];
    }
}

/* ------------------------------------------------------------------ */
extern "C" void kernel_launch(void* const* d_in, const int* in_sizes, int n_in,
                              void* d_out, int out_size)
{
    const float* rules  = (const float*)d_in[0];
    const int*   id1    = (const int*)  d_in[1];
    const int*   id2    = (const int*)  d_in[2];
    const float* W_rule = (const float*)d_in[3];
    const float* b_rule = (const float*)d_in[4];
    const float* face   = (const float*)d_in[5];
    const float* W_ih   = (const float*)d_in[6];
    const float* W_hh   = (const float*)d_in[7];
    const float* b_ih   = (const float*)d_in[8];
    const float* b_hh   = (const float*)d_in[9];
    const float* W_out  = (const float*)d_in[10];
    const float* b_out  = (const float*)d_in[11];
    float* out = (float*)d_out;

    poison_k<<<2048, 256>>>();
    build_x_k<<<SEQ, 256>>>(rules, id1, id2, W_rule, b_rule, face);
    gemm_gx_k<<<dim3(G4 / BN, SEQ / BM), 256>>>(W_ih, b_ih, b_hh);
    lstm_seq_k<<<NCTA, 256>>>(W_hh);
    out_k<<<NSAMP, 256>>>(W_out, b_out, out);
}

// round 14
// speedup vs baseline: 1.7694x; 1.7694x over previous
#include <cuda_runtime.h>
#include <math.h>

#define NSAMP 8192
#define SEQ   (NSAMP*3)      /* 24576 sequential LSTM steps */
#define E     1024
#define HH    1024
#define G4    4096
#define RULED 32
#define OUTD  2
#define NCTA  128
#define POISON 0xFFFFFFFFu   /* NaN bit pattern; h = o*tanh(c) in (-1,1) never matches */

/* Static device scratch — 256B-aligned so vector (128-bit) accesses are legal */
__device__ __align__(256) float g_X [(size_t)SEQ * E];        /* ~100 MB */
__device__ __align__(256) float g_Gx[(size_t)SEQ * G4];       /* ~403 MB */
__device__ __align__(256) float g_h [(size_t)(SEQ + 1) * HH]; /* ~100 MB */

/* ------------------------------------------------------------------ */
/* Init: h row 0 = 0.0f, rows 1..SEQ = NaN poison (data IS the flag). */
__global__ __launch_bounds__(256) void poison_k()
{
    const size_t total = (size_t)(SEQ + 1) * HH;
    unsigned* p = (unsigned*)g_h;
    for (size_t i = (size_t)blockIdx.x * 256 + threadIdx.x; i < total;
         i += (size_t)gridDim.x * 256)
        p[i] = (i < HH) ? 0u : POISON;
}

/* ------------------------------------------------------------------ */
/* Build X: row 3n = rules@W_rule + b_rule, rows 3n+1/2 = face gather */
__global__ __launch_bounds__(256) void build_x_k(
    const float* __restrict__ rules, const int* __restrict__ id1,
    const int* __restrict__ id2, const float* __restrict__ W_rule,
    const float* __restrict__ b_rule, const float* __restrict__ face)
{
    int s = blockIdx.x;
    int n = s / 3, t = s - n * 3;
    float* dst = g_X + (size_t)s * E;
    if (t == 0) {
        __shared__ float r[RULED];
        if (threadIdx.x < RULED) r[threadIdx.x] = rules[n * RULED + threadIdx.x];
        __syncthreads();
        for (int e = threadIdx.x; e < E; e += 256) {
            float acc = b_rule[e];
            #pragma unroll
            for (int k = 0; k < RULED; ++k) acc += r[k] * W_rule[k * E + e];
            dst[e] = acc;
        }
    } else {
        int id = (t == 1 ? id1 : id2)[n];
        const float4* src = (const float4*)(face + (size_t)id * E);
        float4* d4 = (float4*)dst;
        for (int i = threadIdx.x; i < E / 4; i += 256) d4[i] = src[i];
    }
}

/* ------------------------------------------------------------------ */
/* Gx[s][r] = dot(X[s,:], W_ih[r,:]) + b_ih[r] + b_hh[r]  (C = A B^T) */
#define BM 128
#define BN 128
#define BK 16
__global__ __launch_bounds__(256) void gemm_gx_k(
    const float* __restrict__ B,          /* W_ih [4096][1024] */
    const float* __restrict__ bih, const float* __restrict__ bhh)
{
    __shared__ float As[BK][BM + 4];
    __shared__ float Bs[BK][BN + 4];
    const int bm = blockIdx.y * BM;
    const int bn = blockIdx.x * BN;
    const int tid = threadIdx.x;
    const int ty = tid >> 4, tx = tid & 15;
    float acc[8][8] = {};
    const float* A = g_X;

    for (int k0 = 0; k0 < E; k0 += BK) {
        #pragma unroll
        for (int v = 0; v < 2; ++v) {
            int f4  = tid * 2 + v;
            int row = f4 >> 2;
            int kq  = f4 & 3;
            float4 a = *(const float4*)(A + (size_t)(bm + row) * E + k0 + kq * 4);
            As[kq*4+0][row] = a.x; As[kq*4+1][row] = a.y;
            As[kq*4+2][row] = a.z; As[kq*4+3][row] = a.w;
            float4 b = *(const float4*)(B + (size_t)(bn + row) * E + k0 + kq * 4);
            Bs[kq*4+0][row] = b.x; Bs[kq*4+1][row] = b.y;
            Bs[kq*4+2][row] = b.z; Bs[kq*4+3][row] = b.w;
        }
        __syncthreads();
        #pragma unroll
        for (int k = 0; k < BK; ++k) {
            float ar[8], br[8];
            #pragma unroll
            for (int i = 0; i < 8; ++i) ar[i] = As[k][ty*8 + i];
            #pragma unroll
            for (int i = 0; i < 8; ++i) br[i] = Bs[k][tx*8 + i];
            #pragma unroll
            for (int i = 0; i < 8; ++i)
                #pragma unroll
                for (int j = 0; j < 8; ++j) acc[i][j] += ar[i] * br[j];
        }
        __syncthreads();
    }
    #pragma unroll
    for (int i = 0; i < 8; ++i) {
        size_t row = (size_t)(bm + ty*8 + i);
        #pragma unroll
        for (int j = 0; j < 8; ++j) {
            int col = bn + tx*8 + j;
            g_Gx[row * G4 + col] = acc[i][j] + bih[col] + bhh[col];
        }
    }
}

/* ------------------------------------------------------------------ */
/* Persistent sequential LSTM — R5 core (fastest measured), with 3    */
/* minimal deltas: v4 single-instruction poll, nanosleep on re-poll,  */
/* Gx prefetched one step ahead. Body math bit-identical to R5.       */
__global__ __launch_bounds__(256, 1) void lstm_seq_k(const float* __restrict__ Whh)
{
    const int b    = blockIdx.x;
    const int tid  = threadIdx.x;
    const int warp = tid >> 5;
    const int lane = tid & 31;
    const int j    = b * 8 + warp;

    /* Weight registers: w[q][i] = W_hh[q*1024 + j][lane + 32*i]  (R5) */
    float w[4][32];
    #pragma unroll
    for (int q = 0; q < 4; ++q) {
        const float* wr = Whh + (size_t)(q * HH + j) * HH;
        #pragma unroll
        for (int i = 0; i < 32; ++i) w[q][i] = wr[lane + 32 * i];
    }

    __shared__ __align__(16) float hs[2][HH];   /* double buffer */
    float c = 0.0f;

    /* Gx prefetch pipeline: gq holds step-t value, loaded 1 step ahead */
    float gq = 0.0f;
    if (lane < 4) gq = __ldg(&g_Gx[(size_t)0 * G4 + lane * HH + j]);

    for (int t = 0; t < SEQ; ++t) {
        /* issue NEXT step's gate-bias load now — a full step of overlap */
        float gq_n = 0.0f;
        if (lane < 4 && t + 1 < SEQ)
            gq_n = __ldg(&g_Gx[(size_t)(t + 1) * G4 + lane * HH + j]);

        /* poll own 16B of h(t): ONE volatile v4 load per round (4x fewer
           LSU ops than R5's scalar poll); nanosleep only on a miss.    */
        const unsigned* src = (const unsigned*)g_h + (size_t)t * HH + 4 * tid;
        unsigned u0, u1, u2, u3;
        asm volatile("ld.volatile.global.v4.u32 {%0,%1,%2,%3},[%4];"
                     : "=r"(u0), "=r"(u1), "=r"(u2), "=r"(u3) : "l"(src));
        while (u0 == POISON || u1 == POISON || u2 == POISON || u3 == POISON) {
            __nanosleep(32);
            asm volatile("ld.volatile.global.v4.u32 {%0,%1,%2,%3},[%4];"
                         : "=r"(u0), "=r"(u1), "=r"(u2), "=r"(u3) : "l"(src));
        }

        const int p = t & 1;
        *(float4*)&hs[p][4 * tid] =
            make_float4(__uint_as_float(u0), __uint_as_float(u1),
                        __uint_as_float(u2), __uint_as_float(u3));
        __syncthreads();

        /* R5 dot: 4 gate rows, k strided by lane (bank-conflict free) */
        float a0 = 0.f, a1 = 0.f, a2 = 0.f, a3 = 0.f;
        #pragma unroll
        for (int i = 0; i < 32; ++i) {
            float hv = hs[p][lane + 32 * i];
            a0 += w[0][i] * hv; a1 += w[1][i] * hv;
            a2 += w[2][i] * hv; a3 += w[3][i] * hv;
        }
        #pragma unroll
        for (int off = 16; off; off >>= 1) {
            a0 += __shfl_xor_sync(0xffffffffu, a0, off);
            a1 += __shfl_xor_sync(0xffffffffu, a1, off);
            a2 += __shfl_xor_sync(0xffffffffu, a2, off);
            a3 += __shfl_xor_sync(0xffffffffu, a3, off);
        }

        /* R5 activations: lanes 0..3 compute i,f,g,o in parallel      */
        float pre = ((lane == 0) ? a0 : (lane == 1) ? a1 :
                     (lane == 2) ? a2 : a3) + gq;
        float act = (lane == 2) ? __tanhf(pre)
                                : __fdividef(1.0f, 1.0f + __expf(-pre));
        float iact = __shfl_sync(0xffffffffu, act, 0);
        float fact = __shfl_sync(0xffffffffu, act, 1);
        float gact = __shfl_sync(0xffffffffu, act, 2);
        float oact = __shfl_sync(0xffffffffu, act, 3);

        c = fact * c + iact * gact;
        float hn = oact * __tanhf(c);

        /* publish h(t+1): the stored value is itself the ready flag */
        if (lane == 0)
            __stcg(g_h + (size_t)(t + 1) * HH + j, hn);

        gq = gq_n;              /* rotate the prefetch pipeline */
    }
}

/* ------------------------------------------------------------------ */
/* out[n] = h(after sample n) @ W_out + b_out                          */
__global__ __launch_bounds__(256) void out_k(
    const float* __restrict__ Wout, const float* __restrict__ bout,
    float* __restrict__ out)
{
    int n = blockIdx.x;
    const float* h = g_h + (size_t)(3 * n + 3) * HH;
    float p0 = 0.f, p1 = 0.f;
    for (int jj = threadIdx.x; jj < HH; jj += 256) {
        float hv = h[jj];
        p0 += hv * Wout[jj * 2 + 0];
        p1 += hv * Wout[jj * 2 + 1];
    }
    __shared__ float s0[256], s1[256];
    s0[threadIdx.x] = p0; s1[threadIdx.x] = p1;
    __syncthreads();
    for (int st = 128; st; st >>= 1) {
        if (threadIdx.x < st) {
            s0[threadIdx.x] += s0[threadIdx.x + st];
            s1[threadIdx.x] += s1[threadIdx.x + st];
        }
        __syncthreads();
    }
    if (threadIdx.x == 0) {
        out[n * 2 + 0] = s0[0] + bout[0];
        out[n * 2 + 1] = s1[0] + bout[1];
    }
}

/* ------------------------------------------------------------------ */
extern "C" void kernel_launch(void* const* d_in, const int* in_sizes, int n_in,
                              void* d_out, int out_size)
{
    const float* rules  = (const float*)d_in[0];
    const int*   id1    = (const int*)  d_in[1];
    const int*   id2    = (const int*)  d_in[2];
    const float* W_rule = (const float*)d_in[3];
    const float* b_rule = (const float*)d_in[4];
    const float* face   = (const float*)d_in[5];
    const float* W_ih   = (const float*)d_in[6];
    const float* W_hh   = (const float*)d_in[7];
    const float* b_ih   = (const float*)d_in[8];
    const float* b_hh   = (const float*)d_in[9];
    const float* W_out  = (const float*)d_in[10];
    const float* b_out  = (const float*)d_in[11];
    float* out = (float*)d_out;

    poison_k<<<2048, 256>>>();
    build_x_k<<<SEQ, 256>>>(rules, id1, id2, W_rule, b_rule, face);
    gemm_gx_k<<<dim3(G4 / BN, SEQ / BM), 256>>>(W_ih, b_ih, b_hh);
    lstm_seq_k<<<NCTA, 256>>>(W_hh);
    out_k<<<NSAMP, 256>>>(W_out, b_out, out);
}

// round 15
// speedup vs baseline: 2.5047x; 1.4155x over previous
#include <cuda_runtime.h>
#include <math.h>

#define NSAMP 8192
#define SEQ   (NSAMP*3)      /* 24576 sequential LSTM steps */
#define E     1024
#define HH    1024
#define G4    4096
#define RULED 32
#define OUTD  2
#define NCTA  128
#define POISON 0xFFFFFFFFu   /* NaN bit pattern; h = o*tanh(c) in (-1,1) never matches */

/* Static device scratch — 256B-aligned so vector (128-bit) accesses are legal */
__device__ __align__(256) float g_X [(size_t)SEQ * E];        /* ~100 MB */
__device__ __align__(256) float g_Gx[(size_t)SEQ * G4];       /* ~403 MB */
__device__ __align__(256) float g_h [(size_t)(SEQ + 1) * HH]; /* ~100 MB */

/* ------------------------------------------------------------------ */
/* Init: h row 0 = 0.0f, rows 1..SEQ = NaN poison (data IS the flag). */
__global__ __launch_bounds__(256) void poison_k()
{
    const size_t total = (size_t)(SEQ + 1) * HH;
    unsigned* p = (unsigned*)g_h;
    for (size_t i = (size_t)blockIdx.x * 256 + threadIdx.x; i < total;
         i += (size_t)gridDim.x * 256)
        p[i] = (i < HH) ? 0u : POISON;
}

/* ------------------------------------------------------------------ */
/* Build X: row 3n = rules@W_rule + b_rule, rows 3n+1/2 = face gather */
__global__ __launch_bounds__(256) void build_x_k(
    const float* __restrict__ rules, const int* __restrict__ id1,
    const int* __restrict__ id2, const float* __restrict__ W_rule,
    const float* __restrict__ b_rule, const float* __restrict__ face)
{
    int s = blockIdx.x;
    int n = s / 3, t = s - n * 3;
    float* dst = g_X + (size_t)s * E;
    if (t == 0) {
        __shared__ float r[RULED];
        if (threadIdx.x < RULED) r[threadIdx.x] = rules[n * RULED + threadIdx.x];
        __syncthreads();
        for (int e = threadIdx.x; e < E; e += 256) {
            float acc = b_rule[e];
            #pragma unroll
            for (int k = 0; k < RULED; ++k) acc += r[k] * W_rule[k * E + e];
            dst[e] = acc;
        }
    } else {
        int id = (t == 1 ? id1 : id2)[n];
        const float4* src = (const float4*)(face + (size_t)id * E);
        float4* d4 = (float4*)dst;
        for (int i = threadIdx.x; i < E / 4; i += 256) d4[i] = src[i];
    }
}

/* ------------------------------------------------------------------ */
/* Gx[s][r] = dot(X[s,:], W_ih[r,:]) + b_ih[r] + b_hh[r]  (C = A B^T) */
#define BM 128
#define BN 128
#define BK 16
__global__ __launch_bounds__(256) void gemm_gx_k(
    const float* __restrict__ B,          /* W_ih [4096][1024] */
    const float* __restrict__ bih, const float* __restrict__ bhh)
{
    __shared__ float As[BK][BM + 4];
    __shared__ float Bs[BK][BN + 4];
    const int bm = blockIdx.y * BM;
    const int bn = blockIdx.x * BN;
    const int tid = threadIdx.x;
    const int ty = tid >> 4, tx = tid & 15;
    float acc[8][8] = {};
    const float* A = g_X;

    for (int k0 = 0; k0 < E; k0 += BK) {
        #pragma unroll
        for (int v = 0; v < 2; ++v) {
            int f4  = tid * 2 + v;
            int row = f4 >> 2;
            int kq  = f4 & 3;
            float4 a = *(const float4*)(A + (size_t)(bm + row) * E + k0 + kq * 4);
            As[kq*4+0][row] = a.x; As[kq*4+1][row] = a.y;
            As[kq*4+2][row] = a.z; As[kq*4+3][row] = a.w;
            float4 b = *(const float4*)(B + (size_t)(bn + row) * E + k0 + kq * 4);
            Bs[kq*4+0][row] = b.x; Bs[kq*4+1][row] = b.y;
            Bs[kq*4+2][row] = b.z; Bs[kq*4+3][row] = b.w;
        }
        __syncthreads();
        #pragma unroll
        for (int k = 0; k < BK; ++k) {
            float ar[8], br[8];
            #pragma unroll
            for (int i = 0; i < 8; ++i) ar[i] = As[k][ty*8 + i];
            #pragma unroll
            for (int i = 0; i < 8; ++i) br[i] = Bs[k][tx*8 + i];
            #pragma unroll
            for (int i = 0; i < 8; ++i)
                #pragma unroll
                for (int j = 0; j < 8; ++j) acc[i][j] += ar[i] * br[j];
        }
        __syncthreads();
    }
    #pragma unroll
    for (int i = 0; i < 8; ++i) {
        size_t row = (size_t)(bm + ty*8 + i);
        #pragma unroll
        for (int j = 0; j < 8; ++j) {
            int col = bn + tx*8 + j;
            g_Gx[row * G4 + col] = acc[i][j] + bih[col] + bhh[col];
        }
    }
}

/* ------------------------------------------------------------------ */
/* Persistent sequential LSTM — R5 core, ONE structural change:       */
/* aggregated single-transition publishes. Each CTA gathers its 8 hn  */
/* into smem and publishes via two coalesced STG.128 — so every       */
/* consumer 16B poll chunk flips poison->valid in ONE event (no       */
/* partial-fill poll rounds) and store packets drop 1024 -> 256.      */
__global__ __launch_bounds__(256, 1) void lstm_seq_k(const float* __restrict__ Whh)
{
    const int b    = blockIdx.x;
    const int tid  = threadIdx.x;
    const int warp = tid >> 5;
    const int lane = tid & 31;
    const int j    = b * 8 + warp;

    /* Weight registers: w[q][i] = W_hh[q*1024 + j][lane + 32*i]  (R5) */
    float w[4][32];
    #pragma unroll
    for (int q = 0; q < 4; ++q) {
        const float* wr = Whh + (size_t)(q * HH + j) * HH;
        #pragma unroll
        for (int i = 0; i < 32; ++i) w[q][i] = wr[lane + 32 * i];
    }

    __shared__ __align__(16) float hs[2][HH];   /* double buffer */
    __shared__ __align__(16) float hout[8];     /* CTA publish staging */
    float c = 0.0f;

    for (int t = 0; t < SEQ; ++t) {
        /* gate-bias prefetch (R5 style: issued before the poll)       */
        float gq = 0.0f;
        if (lane < 4) gq = __ldg(&g_Gx[(size_t)t * G4 + lane * HH + j]);

        /* poll own 16B of h(t): one volatile v4 load per round.
           Thanks to 16B-atomic publishes, each chunk flips valid in a
           single event — a hit means all 4 floats are valid.          */
        const unsigned* src = (const unsigned*)g_h + (size_t)t * HH + 4 * tid;
        unsigned u0, u1, u2, u3;
        do {
            asm volatile("ld.volatile.global.v4.u32 {%0,%1,%2,%3},[%4];"
                         : "=r"(u0), "=r"(u1), "=r"(u2), "=r"(u3) : "l"(src));
        } while (u0 == POISON || u1 == POISON || u2 == POISON || u3 == POISON);

        const int p = t & 1;
        *(float4*)&hs[p][4 * tid] =
            make_float4(__uint_as_float(u0), __uint_as_float(u1),
                        __uint_as_float(u2), __uint_as_float(u3));
        __syncthreads();                          /* B1: h staged */

        /* R5 dot: 4 gate rows, k strided by lane (bank-conflict free) */
        float a0 = 0.f, a1 = 0.f, a2 = 0.f, a3 = 0.f;
        #pragma unroll
        for (int i = 0; i < 32; ++i) {
            float hv = hs[p][lane + 32 * i];
            a0 += w[0][i] * hv; a1 += w[1][i] * hv;
            a2 += w[2][i] * hv; a3 += w[3][i] * hv;
        }
        #pragma unroll
        for (int off = 16; off; off >>= 1) {
            a0 += __shfl_xor_sync(0xffffffffu, a0, off);
            a1 += __shfl_xor_sync(0xffffffffu, a1, off);
            a2 += __shfl_xor_sync(0xffffffffu, a2, off);
            a3 += __shfl_xor_sync(0xffffffffu, a3, off);
        }

        /* R5 activations: lanes 0..3 compute i,f,g,o in parallel      */
        float pre = ((lane == 0) ? a0 : (lane == 1) ? a1 :
                     (lane == 2) ? a2 : a3) + gq;
        float act = (lane == 2) ? __tanhf(pre)
                                : __fdividef(1.0f, 1.0f + __expf(-pre));
        float iact = __shfl_sync(0xffffffffu, act, 0);
        float fact = __shfl_sync(0xffffffffu, act, 1);
        float gact = __shfl_sync(0xffffffffu, act, 2);
        float oact = __shfl_sync(0xffffffffu, act, 3);

        c = fact * c + iact * gact;
        float hn = oact * __tanhf(c);

        /* aggregated publish: gather 8 hn in smem, then 2 x STG.128.
           Each 16B store makes one consumer chunk valid atomically.   */
        if (lane == 0) hout[warp] = hn;
        __syncthreads();                          /* B2: hout complete */
        if (tid < 2) {
            float4 v = *(const float4*)&hout[tid * 4];
            __stcg((float4*)(g_h + (size_t)(t + 1) * HH + b * 8) + tid, v);
        }
    }
}

/* ------------------------------------------------------------------ */
/* out[n] = h(after sample n) @ W_out + b_out                          */
__global__ __launch_bounds__(256) void out_k(
    const float* __restrict__ Wout, const float* __restrict__ bout,
    float* __restrict__ out)
{
    int n = blockIdx.x;
    const float* h = g_h + (size_t)(3 * n + 3) * HH;
    float p0 = 0.f, p1 = 0.f;
    for (int jj = threadIdx.x; jj < HH; jj += 256) {
        float hv = h[jj];
        p0 += hv * Wout[jj * 2 + 0];
        p1 += hv * Wout[jj * 2 + 1];
    }
    __shared__ float s0[256], s1[256];
    s0[threadIdx.x] = p0; s1[threadIdx.x] = p1;
    __syncthreads();
    for (int st = 128; st; st >>= 1) {
        if (threadIdx.x < st) {
            s0[threadIdx.x] += s0[threadIdx.x + st];
            s1[threadIdx.x] += s1[threadIdx.x + st];
        }
        __syncthreads();
    }
    if (threadIdx.x == 0) {
        out[n * 2 + 0] = s0[0] + bout[0];
        out[n * 2 + 1] = s1[0] + bout[1];
    }
}

/* ------------------------------------------------------------------ */
extern "C" void kernel_launch(void* const* d_in, const int* in_sizes, int n_in,
                              void* d_out, int out_size)
{
    const float* rules  = (const float*)d_in[0];
    const int*   id1    = (const int*)  d_in[1];
    const int*   id2    = (const int*)  d_in[2];
    const float* W_rule = (const float*)d_in[3];
    const float* b_rule = (const float*)d_in[4];
    const float* face   = (const float*)d_in[5];
    const float* W_ih   = (const float*)d_in[6];
    const float* W_hh   = (const float*)d_in[7];
    const float* b_ih   = (const float*)d_in[8];
    const float* b_hh   = (const float*)d_in[9];
    const float* W_out  = (const float*)d_in[10];
    const float* b_out  = (const float*)d_in[11];
    float* out = (float*)d_out;

    poison_k<<<2048, 256>>>();
    build_x_k<<<SEQ, 256>>>(rules, id1, id2, W_rule, b_rule, face);
    gemm_gx_k<<<dim3(G4 / BN, SEQ / BM), 256>>>(W_ih, b_ih, b_hh);
    lstm_seq_k<<<NCTA, 256>>>(W_hh);
    out_k<<<NSAMP, 256>>>(W_out, b_out, out);
}